// round 4
// baseline (speedup 1.0000x reference)
#include <cuda_runtime.h>
#include <cuda_bf16.h>
#include <math.h>

#define NTOK   131072
#define NCODE  2048
#define DIM    64
#define BM     128
#define BN     128

// Output layout (tuple flattened):
#define OFF_XOUT   0
#define OFF_COMMIT 8388608
#define OFF_PERP   8388609
#define OFF_NCB    8388610
#define OFF_NSUM   8519682
#define OFF_NCNT   8650754

// ---- device scratch (no allocations allowed) ----
__device__ int   g_idx[NTOK];
__device__ float g_xnorm[NTOK];
__device__ float g_cnorm[NCODE];
__device__ float g_sumb[NCODE * DIM];
__device__ float g_cntb[NCODE];
__device__ float g_commit;
__device__ float g_plog;

typedef unsigned long long u64;

__device__ __forceinline__ u64 pk(float lo, float hi) {
    u64 r; asm("mov.b64 %0, {%1,%2};" : "=l"(r) : "f"(lo), "f"(hi)); return r;
}
__device__ __forceinline__ void fma2(u64& d, u64 a, u64 b) {
    asm("fma.rn.f32x2 %0, %1, %2, %0;" : "+l"(d) : "l"(a), "l"(b));
}
__device__ __forceinline__ float2 up(u64 v) {
    float2 r; asm("mov.b64 {%0,%1}, %2;" : "=f"(r.x), "=f"(r.y) : "l"(v)); return r;
}

// ---- K0: zero accumulators ----
__global__ void k_zero() {
    int i = blockIdx.x * 256 + threadIdx.x;
    if (i < NCODE * DIM) g_sumb[i] = 0.0f;
    if (i < NCODE)       g_cntb[i] = 0.0f;
    if (i == 0) { g_commit = 0.0f; g_plog = 0.0f; }
}

// ---- K0b: per-code squared norms (rounded squares, then sequential sum) ----
__global__ void k_cnorm(const float* __restrict__ cb) {
    int c = blockIdx.x * 256 + threadIdx.x;
    if (c >= NCODE) return;
    const float4* p = (const float4*)(cb + c * DIM);
    float s = 0.0f;
#pragma unroll
    for (int q = 0; q < 16; q++) {
        float4 v = p[q];
        s = __fadd_rn(s, __fmul_rn(v.x, v.x));
        s = __fadd_rn(s, __fmul_rn(v.y, v.y));
        s = __fadd_rn(s, __fmul_rn(v.z, v.z));
        s = __fadd_rn(s, __fmul_rn(v.w, v.w));
    }
    g_cnorm[c] = s;
}

// ---- K1: distance GEMM + argmin (FFMA2 register-tiled, static 48KB smem) ----
// Block: 128 tokens x all 2048 codes. 256 threads as 16(tn) x 16(tm).
// Each thread: 8 tokens x 8 codes (4 f32x2 code-pair accumulators per token).
// Distance computed as (||x||^2 - 2*dot) + ||c||^2 in the reference's op order
// so that fp32 quantization (and hence argmin ties) match the reference.
__global__ void __launch_bounds__(256) k1_argmin(const float* __restrict__ x,
                                                 const float* __restrict__ cb) {
    __shared__ float xT[64 * 128];   // [k][m]  x tile transposed, full K   (32 KB)
    __shared__ float cT[32 * 128];   // [k][n]  code tile transposed, K/2   (16 KB)

    int tid = threadIdx.x;
    int tn = tid & 15, tm = tid >> 4;
    int m0 = blockIdx.x * BM;

    // Load x tile transposed + per-token ||x||^2 (rounded squares, seq sum)
    {
        int r = tid >> 1, seg = tid & 1;
        const float4* xp = (const float4*)(x + (long)(m0 + r) * DIM + seg * 32);
        float ps = 0.0f;
#pragma unroll
        for (int q = 0; q < 8; q++) {
            float4 v = xp[q];
            int k = seg * 32 + q * 4;
            xT[(k + 0) * 128 + r] = v.x;
            xT[(k + 1) * 128 + r] = v.y;
            xT[(k + 2) * 128 + r] = v.z;
            xT[(k + 3) * 128 + r] = v.w;
            ps = __fadd_rn(ps, __fmul_rn(v.x, v.x));
            ps = __fadd_rn(ps, __fmul_rn(v.y, v.y));
            ps = __fadd_rn(ps, __fmul_rn(v.z, v.z));
            ps = __fadd_rn(ps, __fmul_rn(v.w, v.w));
        }
        // combine the two 32-element halves (lanes tid^1 are partners)
        float other = __shfl_xor_sync(0xffffffffu, ps, 1);
        float xn = (seg == 0) ? __fadd_rn(ps, other) : __fadd_rn(other, ps);
        if (seg == 0) g_xnorm[m0 + r] = xn;
    }
    __syncthreads();

    // each thread caches ||x||^2 for its 8 tokens
    float xnr[8];
#pragma unroll
    for (int i = 0; i < 8; i++) xnr[i] = g_xnorm[m0 + tm * 8 + i];

    float bv[8];
    int   bi[8];
#pragma unroll
    for (int i = 0; i < 8; i++) { bv[i] = 3.4e38f; bi[i] = 0; }

    u64 acc[8][4];

    for (int n0 = 0; n0 < NCODE; n0 += BN) {
#pragma unroll
        for (int i = 0; i < 8; i++)
#pragma unroll
            for (int j = 0; j < 4; j++) acc[i][j] = 0ull;

#pragma unroll
        for (int h = 0; h < 2; h++) {
            __syncthreads();
            {   // load code tile half: cT[k'][n], k' in [0,32), codes n0..n0+127
                int r = tid >> 1, seg = tid & 1;
                const float4* cp = (const float4*)(cb + (long)(n0 + r) * DIM + h * 32 + seg * 16);
#pragma unroll
                for (int q = 0; q < 4; q++) {
                    float4 v = cp[q];
                    int k = seg * 16 + q * 4;
                    cT[(k + 0) * 128 + r] = v.x;
                    cT[(k + 1) * 128 + r] = v.y;
                    cT[(k + 2) * 128 + r] = v.z;
                    cT[(k + 3) * 128 + r] = v.w;
                }
            }
            __syncthreads();

#pragma unroll 4
            for (int k = 0; k < 32; k++) {
                const float4 xa = *(const float4*)&xT[(h * 32 + k) * 128 + tm * 8];
                const float4 xb = *(const float4*)&xT[(h * 32 + k) * 128 + tm * 8 + 4];
                const float4 ca = *(const float4*)&cT[k * 128 + tn * 8];
                const float4 cc = *(const float4*)&cT[k * 128 + tn * 8 + 4];
                u64 b0 = pk(ca.x, ca.y), b1 = pk(ca.z, ca.w);
                u64 b2 = pk(cc.x, cc.y), b3 = pk(cc.z, cc.w);
                float xs[8] = {xa.x, xa.y, xa.z, xa.w, xb.x, xb.y, xb.z, xb.w};
#pragma unroll
                for (int i = 0; i < 8; i++) {
                    u64 a = pk(xs[i], xs[i]);
                    fma2(acc[i][0], a, b0);
                    fma2(acc[i][1], a, b1);
                    fma2(acc[i][2], a, b2);
                    fma2(acc[i][3], a, b3);
                }
            }
        }

        // epilogue: score = (||x||^2 - 2*dot) + ||c||^2, reference op order.
        // running argmin with strict < keeps lowest index.
        float cn[8];
#pragma unroll
        for (int j = 0; j < 8; j++) cn[j] = __ldg(&g_cnorm[n0 + tn * 8 + j]);
#pragma unroll
        for (int i = 0; i < 8; i++) {
#pragma unroll
            for (int j = 0; j < 4; j++) {
                float2 v = up(acc[i][j]);
                int cidx = n0 + tn * 8 + 2 * j;
                float s0 = __fadd_rn(__fsub_rn(xnr[i], __fmul_rn(2.0f, v.x)), cn[2 * j]);
                float s1 = __fadd_rn(__fsub_rn(xnr[i], __fmul_rn(2.0f, v.y)), cn[2 * j + 1]);
                if (s0 < bv[i]) { bv[i] = s0; bi[i] = cidx; }
                if (s1 < bv[i]) { bv[i] = s1; bi[i] = cidx + 1; }
            }
        }
    }

    // cross-thread reduction over the 16 tn-groups (reuse cT: 2048 fl + 2048 int)
    __syncthreads();
    float* rv = cT;
    int*   ri = (int*)(cT + 16 * 128);
#pragma unroll
    for (int i = 0; i < 8; i++) {
        rv[tn * 128 + tm * 8 + i] = bv[i];
        ri[tn * 128 + tm * 8 + i] = bi[i];
    }
    __syncthreads();
    if (tid < 128) {
        float best = rv[tid];
        int bidx = ri[tid];
#pragma unroll
        for (int t = 1; t < 16; t++) {
            float v = rv[t * 128 + tid];
            int  id = ri[t * 128 + tid];
            if (v < best || (v == best && id < bidx)) { best = v; bidx = id; }
        }
        g_idx[m0 + tid] = bidx;
    }
}

// ---- K2: gather x_d, write x_out = x + (x_d - x) (reference rounding),
//          segment-sum scatter, commit loss. 4 threads per token, 16 dims each.
__global__ void k_scatter(const float* __restrict__ x, const float* __restrict__ cb,
                          float* __restrict__ out) {
    int gt = blockIdx.x * blockDim.x + threadIdx.x;
    int t = gt >> 2, part = gt & 3;
    int idx = g_idx[t];
    const float4* xp = (const float4*)(x + (long)t * DIM + part * 16);
    const float4* cp = (const float4*)(cb + (long)idx * DIM + part * 16);
    float4* op = (float4*)(out + OFF_XOUT + (long)t * DIM + part * 16);
    float* sb = &g_sumb[idx * DIM + part * 16];
    float cs = 0.0f;
#pragma unroll
    for (int q = 0; q < 4; q++) {
        float4 xv = xp[q];
        float4 cv = cp[q];
        float4 o;
        o.x = __fadd_rn(xv.x, __fsub_rn(cv.x, xv.x));
        o.y = __fadd_rn(xv.y, __fsub_rn(cv.y, xv.y));
        o.z = __fadd_rn(xv.z, __fsub_rn(cv.z, xv.z));
        o.w = __fadd_rn(xv.w, __fsub_rn(cv.w, xv.w));
        op[q] = o;
        float dx = __fsub_rn(xv.x, cv.x), dy = __fsub_rn(xv.y, cv.y);
        float dz = __fsub_rn(xv.z, cv.z), dw = __fsub_rn(xv.w, cv.w);
        cs += dx * dx + dy * dy + dz * dz + dw * dw;
        atomicAdd(sb + q * 4 + 0, xv.x);
        atomicAdd(sb + q * 4 + 1, xv.y);
        atomicAdd(sb + q * 4 + 2, xv.z);
        atomicAdd(sb + q * 4 + 3, xv.w);
    }
    if (part == 0) atomicAdd(&g_cntb[idx], 1.0f);
#pragma unroll
    for (int o = 16; o; o >>= 1) cs += __shfl_xor_sync(0xffffffff, cs, o);
    if ((threadIdx.x & 31) == 0) atomicAdd(&g_commit, cs);
}

// ---- K3: EMA update, new codebook, perplexity partials ----
__global__ void k_final(const float* __restrict__ x, const float* __restrict__ code_sum,
                        const float* __restrict__ code_count, float* __restrict__ out) {
    int i = blockIdx.x * 256 + threadIdx.x;   // over NCODE*DIM
    int c = i >> 6, d = i & 63;
    float cntb = g_cntb[c];
    float ncnt = 0.99f * code_count[c] + 0.01f * cntb;
    float ns = 0.99f * code_sum[i] + 0.01f * g_sumb[i];
    out[OFF_NSUM + i] = ns;
    bool used = (ncnt >= 1.0f);
    float refreshed = ns / fmaxf(ncnt, 1e-8f);
    out[OFF_NCB + i] = used ? refreshed : x[i];   // x[:NCODE] flattened == x[i]
    if (d == 0) {
        out[OFF_NCNT + c] = ncnt;
        float p = cntb * (1.0f / 131072.0f);
        atomicAdd(&g_plog, p * logf(p + 1e-7f));
    }
}

// ---- K4: scalars ----
__global__ void k_scalars(float* __restrict__ out) {
    out[OFF_COMMIT] = g_commit * (1.0f / 8388608.0f);
    out[OFF_PERP]   = expf(-g_plog);
}

extern "C" void kernel_launch(void* const* d_in, const int* in_sizes, int n_in,
                              void* d_out, int out_size) {
    const float* x     = (const float*)d_in[0];
    const float* cb    = (const float*)d_in[1];
    const float* csum  = (const float*)d_in[2];
    const float* ccnt  = (const float*)d_in[3];
    float* out = (float*)d_out;

    k_zero<<<512, 256>>>();
    k_cnorm<<<8, 256>>>(cb);
    k1_argmin<<<NTOK / BM, 256>>>(x, cb);
    k_scatter<<<NTOK * 4 / 256, 256>>>(x, cb, out);
    k_final<<<NCODE * DIM / 256, 256>>>(x, csum, ccnt, out);
    k_scalars<<<1, 1>>>(out);
}

// round 6
// speedup vs baseline: 1.0504x; 1.0504x over previous
#include <cuda_runtime.h>
#include <cuda_bf16.h>
#include <math.h>

#define NTOK   131072
#define NCODE  2048
#define DIM    64
#define BM     128
#define BN     128

// Output layout (tuple flattened):
#define OFF_XOUT   0
#define OFF_COMMIT 8388608
#define OFF_PERP   8388609
#define OFF_NCB    8388610
#define OFF_NSUM   8519682
#define OFF_NCNT   8650754

// ---- device scratch (no allocations allowed) ----
__device__ int   g_idx[NTOK];
__device__ float g_xnorm[NTOK];
__device__ float g_cnorm[NCODE];
__device__ float g_sumb[NCODE * DIM];
__device__ float g_cntb[NCODE];
__device__ float g_commit;
__device__ float g_plog;

typedef unsigned long long u64;

__device__ __forceinline__ void fma2(u64& d, u64 a, u64 b) {
    asm("fma.rn.f32x2 %0, %1, %2, %0;" : "+l"(d) : "l"(a), "l"(b));
}
__device__ __forceinline__ float2 up(u64 v) {
    float2 r; asm("mov.b64 {%0,%1}, %2;" : "=f"(r.x), "=f"(r.y) : "l"(v)); return r;
}

// ---- K0: zero accumulators ----
__global__ void k_zero() {
    int i = blockIdx.x * 256 + threadIdx.x;
    if (i < NCODE * DIM) g_sumb[i] = 0.0f;
    if (i < NCODE)       g_cntb[i] = 0.0f;
    if (i == 0) { g_commit = 0.0f; g_plog = 0.0f; }
}

// ---- K0b: per-code squared norms (rounded squares, then sequential sum) ----
__global__ void k_cnorm(const float* __restrict__ cb) {
    int c = blockIdx.x * 256 + threadIdx.x;
    if (c >= NCODE) return;
    const float4* p = (const float4*)(cb + c * DIM);
    float s = 0.0f;
#pragma unroll
    for (int q = 0; q < 16; q++) {
        float4 v = p[q];
        s = __fadd_rn(s, __fmul_rn(v.x, v.x));
        s = __fadd_rn(s, __fmul_rn(v.y, v.y));
        s = __fadd_rn(s, __fmul_rn(v.z, v.z));
        s = __fadd_rn(s, __fmul_rn(v.w, v.w));
    }
    g_cnorm[c] = s;
}

// ---- K1: distance GEMM + argmin ----
// FFMA2 register-tiled, MOV-free mainloop: both f32x2 operands live in smem
// as 64-bit values (x pre-duplicated, code pairs naturally adjacent).
// Block: 128 tokens x all 2048 codes. 256 threads as 16(tn) x 16(tm),
// each thread 8 tokens x 8 codes. 96KB dynamic smem, 2 blocks/SM.
__global__ void __launch_bounds__(256, 2) k1_argmin(const float* __restrict__ x,
                                                    const float* __restrict__ cb) {
    extern __shared__ float sm[];
    float* xDf = sm;            // [64][128][2]  x duplicated pairs (64 KB)
    float* cT  = sm + 16384;    // [64][128]     code tile transposed (32 KB)

    int tid = threadIdx.x;
    int tn = tid & 15, tm = tid >> 4;
    int m0 = blockIdx.x * BM;

    // Load x tile (duplicated) + per-token ||x||^2 (rounded squares, seq sum)
    {
        int r = tid >> 1, seg = tid & 1;
        const float4* xp = (const float4*)(x + (long)(m0 + r) * DIM + seg * 32);
        float ps = 0.0f;
#pragma unroll
        for (int q = 0; q < 8; q++) {
            float4 v = xp[q];
            int k = seg * 32 + q * 4;
            float2* d0 = (float2*)&xDf[((k + 0) * 128 + r) * 2];
            float2* d1 = (float2*)&xDf[((k + 1) * 128 + r) * 2];
            float2* d2 = (float2*)&xDf[((k + 2) * 128 + r) * 2];
            float2* d3 = (float2*)&xDf[((k + 3) * 128 + r) * 2];
            *d0 = make_float2(v.x, v.x);
            *d1 = make_float2(v.y, v.y);
            *d2 = make_float2(v.z, v.z);
            *d3 = make_float2(v.w, v.w);
            ps = __fadd_rn(ps, __fmul_rn(v.x, v.x));
            ps = __fadd_rn(ps, __fmul_rn(v.y, v.y));
            ps = __fadd_rn(ps, __fmul_rn(v.z, v.z));
            ps = __fadd_rn(ps, __fmul_rn(v.w, v.w));
        }
        float other = __shfl_xor_sync(0xffffffffu, ps, 1);
        float xn = (seg == 0) ? __fadd_rn(ps, other) : __fadd_rn(other, ps);
        if (seg == 0) g_xnorm[m0 + r] = xn;
    }

    float bv[8];
    int   bi[8];
#pragma unroll
    for (int i = 0; i < 8; i++) { bv[i] = 3.4e38f; bi[i] = 0; }

    u64 acc[8][4];
    float xnr[8];
    bool have_xn = false;

    for (int n0 = 0; n0 < NCODE; n0 += BN) {
        __syncthreads();
        {   // load code tile transposed: cT[k][n], codes n0..n0+127, full K
            int r = tid >> 1, seg = tid & 1;
            const float4* cp = (const float4*)(cb + (long)(n0 + r) * DIM + seg * 32);
#pragma unroll
            for (int q = 0; q < 8; q++) {
                float4 v = cp[q];
                int k = seg * 32 + q * 4;
                cT[(k + 0) * 128 + r] = v.x;
                cT[(k + 1) * 128 + r] = v.y;
                cT[(k + 2) * 128 + r] = v.z;
                cT[(k + 3) * 128 + r] = v.w;
            }
        }
        __syncthreads();

        if (!have_xn) {   // after first sync, xD writes visible; cache ||x||^2
#pragma unroll
            for (int i = 0; i < 8; i++) xnr[i] = g_xnorm[m0 + tm * 8 + i];
            have_xn = true;
        }

#pragma unroll
        for (int i = 0; i < 8; i++)
#pragma unroll
            for (int j = 0; j < 4; j++) acc[i][j] = 0ull;

#pragma unroll 4
        for (int k = 0; k < 64; k++) {
            // a: duplicated x pairs for tokens tm*8..tm*8+7 (4 x LDS.128)
            const ulonglong2* ap = (const ulonglong2*)&xDf[(k * 128 + tm * 8) * 2];
            ulonglong2 a01 = ap[0], a23 = ap[1], a45 = ap[2], a67 = ap[3];
            // b: code pairs for codes tn*8..tn*8+7 (2 x LDS.128)
            const ulonglong2* bp = (const ulonglong2*)&cT[k * 128 + tn * 8];
            ulonglong2 b03 = bp[0], b47 = bp[1];
            u64 as[8] = {a01.x, a01.y, a23.x, a23.y, a45.x, a45.y, a67.x, a67.y};
#pragma unroll
            for (int i = 0; i < 8; i++) {
                fma2(acc[i][0], as[i], b03.x);
                fma2(acc[i][1], as[i], b03.y);
                fma2(acc[i][2], as[i], b47.x);
                fma2(acc[i][3], as[i], b47.y);
            }
        }

        // epilogue: score = (||x||^2 - 2*dot) + ||c||^2, reference op order.
        float cn[8];
#pragma unroll
        for (int j = 0; j < 8; j++) cn[j] = __ldg(&g_cnorm[n0 + tn * 8 + j]);
#pragma unroll
        for (int i = 0; i < 8; i++) {
#pragma unroll
            for (int j = 0; j < 4; j++) {
                float2 v = up(acc[i][j]);
                int cidx = n0 + tn * 8 + 2 * j;
                float s0 = __fadd_rn(__fsub_rn(xnr[i], __fmul_rn(2.0f, v.x)), cn[2 * j]);
                float s1 = __fadd_rn(__fsub_rn(xnr[i], __fmul_rn(2.0f, v.y)), cn[2 * j + 1]);
                if (s0 < bv[i]) { bv[i] = s0; bi[i] = cidx; }
                if (s1 < bv[i]) { bv[i] = s1; bi[i] = cidx + 1; }
            }
        }
    }

    // cross-thread reduction over the 16 tn-groups (reuse cT: 2048 fl + 2048 int)
    __syncthreads();
    float* rv = cT;
    int*   ri = (int*)(cT + 16 * 128);
#pragma unroll
    for (int i = 0; i < 8; i++) {
        rv[tn * 128 + tm * 8 + i] = bv[i];
        ri[tn * 128 + tm * 8 + i] = bi[i];
    }
    __syncthreads();
    if (tid < 128) {
        float best = rv[tid];
        int bidx = ri[tid];
#pragma unroll
        for (int t = 1; t < 16; t++) {
            float v = rv[t * 128 + tid];
            int  id = ri[t * 128 + tid];
            if (v < best || (v == best && id < bidx)) { best = v; bidx = id; }
        }
        g_idx[m0 + tid] = bidx;
    }
}

// ---- K2: gather x_d, write x_out = x + (x_d - x) (reference rounding),
//          segment-sum scatter, commit loss. 4 threads per token, 16 dims each.
__global__ void k_scatter(const float* __restrict__ x, const float* __restrict__ cb,
                          float* __restrict__ out) {
    int gt = blockIdx.x * blockDim.x + threadIdx.x;
    int t = gt >> 2, part = gt & 3;
    int idx = g_idx[t];
    const float4* xp = (const float4*)(x + (long)t * DIM + part * 16);
    const float4* cp = (const float4*)(cb + (long)idx * DIM + part * 16);
    float4* op = (float4*)(out + OFF_XOUT + (long)t * DIM + part * 16);
    float* sb = &g_sumb[idx * DIM + part * 16];
    float cs = 0.0f;
#pragma unroll
    for (int q = 0; q < 4; q++) {
        float4 xv = xp[q];
        float4 cv = cp[q];
        float4 o;
        o.x = __fadd_rn(xv.x, __fsub_rn(cv.x, xv.x));
        o.y = __fadd_rn(xv.y, __fsub_rn(cv.y, xv.y));
        o.z = __fadd_rn(xv.z, __fsub_rn(cv.z, xv.z));
        o.w = __fadd_rn(xv.w, __fsub_rn(cv.w, xv.w));
        op[q] = o;
        float dx = __fsub_rn(xv.x, cv.x), dy = __fsub_rn(xv.y, cv.y);
        float dz = __fsub_rn(xv.z, cv.z), dw = __fsub_rn(xv.w, cv.w);
        cs += dx * dx + dy * dy + dz * dz + dw * dw;
        atomicAdd(sb + q * 4 + 0, xv.x);
        atomicAdd(sb + q * 4 + 1, xv.y);
        atomicAdd(sb + q * 4 + 2, xv.z);
        atomicAdd(sb + q * 4 + 3, xv.w);
    }
    if (part == 0) atomicAdd(&g_cntb[idx], 1.0f);
#pragma unroll
    for (int o = 16; o; o >>= 1) cs += __shfl_xor_sync(0xffffffff, cs, o);
    if ((threadIdx.x & 31) == 0) atomicAdd(&g_commit, cs);
}

// ---- K3: EMA update, new codebook, perplexity partials ----
__global__ void k_final(const float* __restrict__ x, const float* __restrict__ code_sum,
                        const float* __restrict__ code_count, float* __restrict__ out) {
    int i = blockIdx.x * 256 + threadIdx.x;   // over NCODE*DIM
    int c = i >> 6, d = i & 63;
    float cntb = g_cntb[c];
    float ncnt = 0.99f * code_count[c] + 0.01f * cntb;
    float ns = 0.99f * code_sum[i] + 0.01f * g_sumb[i];
    out[OFF_NSUM + i] = ns;
    bool used = (ncnt >= 1.0f);
    float refreshed = ns / fmaxf(ncnt, 1e-8f);
    out[OFF_NCB + i] = used ? refreshed : x[i];   // x[:NCODE] flattened == x[i]
    if (d == 0) {
        out[OFF_NCNT + c] = ncnt;
        float p = cntb * (1.0f / 131072.0f);
        atomicAdd(&g_plog, p * logf(p + 1e-7f));
    }
}

// ---- K4: scalars ----
__global__ void k_scalars(float* __restrict__ out) {
    out[OFF_COMMIT] = g_commit * (1.0f / 8388608.0f);
    out[OFF_PERP]   = expf(-g_plog);
}

extern "C" void kernel_launch(void* const* d_in, const int* in_sizes, int n_in,
                              void* d_out, int out_size) {
    const float* x     = (const float*)d_in[0];
    const float* cb    = (const float*)d_in[1];
    const float* csum  = (const float*)d_in[2];
    const float* ccnt  = (const float*)d_in[3];
    float* out = (float*)d_out;

    const int smem_k1 = 96 * 1024;   // 64KB xD + 32KB cT
    cudaFuncSetAttribute(k1_argmin, cudaFuncAttributeMaxDynamicSharedMemorySize, smem_k1);

    k_zero<<<512, 256>>>();
    k_cnorm<<<8, 256>>>(cb);
    k1_argmin<<<NTOK / BM, 256, smem_k1>>>(x, cb);
    k_scatter<<<NTOK * 4 / 256, 256>>>(x, cb, out);
    k_final<<<NCODE * DIM / 256, 256>>>(x, csum, ccnt, out);
    k_scalars<<<1, 1>>>(out);
}